// round 12
// baseline (speedup 1.0000x reference)
#include <cuda_runtime.h>
#include <cstdint>
#include <math.h>

// SpatialGlimpse fused, one-shot blocks, two-phase separable stencil.
// R12 = R9 row economy (IR=9) x R11 concurrency (8 CTAs/SM via K4 x-split)
//       x 3-group mbarrier pipelining x parallel copy issue x hoisted addressing.

static constexpr int BATCH  = 64;
static constexpr int H = 512, W = 512, C = 3;
static constexpr int OUTHW  = 64;
static constexpr int NDEPTH = 3;
static constexpr int ROWFL  = W * C;   // 1536 floats per image row
static constexpr int NT     = 256;

template<int K> struct Cfg;
template<> struct Cfg<1> { static constexpr int TILE_I = 8; static constexpr int JW = 64; static constexpr int ROWF = 204; static constexpr int NV = 3; };
template<> struct Cfg<2> { static constexpr int TILE_I = 4; static constexpr int JW = 64; static constexpr int ROWF = 396; static constexpr int NV = 3; };
template<> struct Cfg<4> { static constexpr int TILE_I = 2; static constexpr int JW = 32; static constexpr int ROWF = 396; static constexpr int NV = 5; };
// IR = TILE_I*K + 1 = 9 rows for every depth; 3 mbarrier groups of 3 rows.

static constexpr int NBLK4 = BATCH * 32 * 2;   // 4096 (32 row-tiles x 2 col-tiles)
static constexpr int NBLK2 = BATCH * 16;       // 1024
static constexpr int NBLK1 = BATCH * 8;        // 512
static constexpr int NBLK  = NBLK4 + NBLK2 + NBLK1;   // 5632

// SMEM floats: [0,8) three mbarriers (8B at float idx 0,2,4) | tile 9*RF | hs 9*JW f4
static constexpr int TILE_OFF   = 8;
static constexpr int SMEM_BYTES = (TILE_OFF + 9 * 396 + 9 * 64 * 4) * 4;   // 23504 (K=2 max)

__device__ __forceinline__ uint32_t smem_u32(const void* p) {
    return (uint32_t)__cvta_generic_to_shared(p);
}
__device__ __forceinline__ void mbar_init(uint32_t a, uint32_t cnt) {
    asm volatile("mbarrier.init.shared.b64 [%0], %1;" :: "r"(a), "r"(cnt) : "memory");
}
__device__ __forceinline__ void mbar_expect_tx(uint32_t a, uint32_t bytes) {
    asm volatile("mbarrier.arrive.expect_tx.shared.b64 _, [%0], %1;" :: "r"(a), "r"(bytes) : "memory");
}
__device__ __forceinline__ void mbar_wait(uint32_t a, uint32_t parity) {
    asm volatile(
        "{\n\t"
        ".reg .pred P;\n\t"
        "LAB_WAIT_%=:\n\t"
        "mbarrier.try_wait.parity.acquire.cta.shared::cta.b64 P, [%0], %1, 0x989680;\n\t"
        "@P bra LAB_DONE_%=;\n\t"
        "bra LAB_WAIT_%=;\n\t"
        "LAB_DONE_%=:\n\t"
        "}"
        :: "r"(a), "r"(parity) : "memory");
}
__device__ __forceinline__ void bulk_g2s(uint32_t dst, const void* src, uint32_t bytes, uint32_t mbar) {
    asm volatile(
        "cp.async.bulk.shared::cluster.global.mbarrier::complete_tx::bytes [%0], [%1], %2, [%3];"
        :: "r"(dst), "l"(src), "r"(bytes), "r"(mbar) : "memory");
}

// Horizontal weighted sum of one row window (K+1 pixels x 3 channels).
// SH = sub-float4 shift (compile-time so v[] stays in registers).
template<int K, int SH>
__device__ __forceinline__ void hreduce_one(const float* __restrict__ rowp, float wx, float4& h)
{
    constexpr int NV = Cfg<K>::NV;
    const float hx0 = 1.0f - wx;
    float v[4 * NV];
    const float4* rp = reinterpret_cast<const float4*>(rowp);
#pragma unroll
    for (int t = 0; t < NV; t++) {
        float4 q = rp[t];
        v[4*t+0] = q.x; v[4*t+1] = q.y; v[4*t+2] = q.z; v[4*t+3] = q.w;
    }
    float r0 = hx0 * v[SH + 0] + wx * v[SH + 3*K + 0];
    float r1 = hx0 * v[SH + 1] + wx * v[SH + 3*K + 1];
    float r2 = hx0 * v[SH + 2] + wx * v[SH + 3*K + 2];
#pragma unroll
    for (int q = 1; q < K; q++) {
        r0 += v[SH + 3*q + 0];
        r1 += v[SH + 3*q + 1];
        r2 += v[SH + 3*q + 2];
    }
    h.x = r0; h.y = r1; h.z = r2; h.w = 0.0f;
}

// Phase A over 3 pipelined row-groups with per-thread hoisted addressing.
template<int K>
__device__ __forceinline__ void phaseA_pipelined(
    float* smem, const float* __restrict__ tile, float4* __restrict__ hs,
    int off0, float wx)
{
    constexpr int JW = Cfg<K>::JW;
    constexpr int RF = Cfg<K>::ROWF;
    const int tid  = threadIdx.x;
    const int jA   = tid & (JW - 1);
    const int rsub = tid / JW;                    // row-within-group
    const int sidx = off0 + 3 * K * jA;
    const float* colp = tile + (sidx & ~3);       // hoisted column base
    const int sh = sidx & 3;
    const bool act = tid < 3 * JW;

#pragma unroll
    for (int g = 0; g < 3; g++) {
        mbar_wait(smem_u32(smem + 2 * g), 0);
        if (act) {
            const int r = 3 * g + rsub;
            const float* rowp = colp + r * RF;
            float4 h;
            switch (sh) {
            case 0:  hreduce_one<K,0>(rowp, wx, h); break;
            case 1:  hreduce_one<K,1>(rowp, wx, h); break;
            case 2:  hreduce_one<K,2>(rowp, wx, h); break;
            default: hreduce_one<K,3>(rowp, wx, h); break;
            }
            hs[r * JW + jA] = h;
        }
    }
}

template<int K, int D>
__device__ __forceinline__ void glimpse_body(
    const float* __restrict__ img, const float* __restrict__ offs,
    float* __restrict__ out, float* smem, int b, int i0, int j0)
{
    constexpr int TILE_I = Cfg<K>::TILE_I;
    constexpr int JW     = Cfg<K>::JW;
    constexpr int RF     = Cfg<K>::ROWF;
    constexpr int IR     = 9;
    constexpr int SPAN   = JW * K + 1;

    float* tile = smem + TILE_OFF;
    float4* hs  = reinterpret_cast<float4*>(smem + TILE_OFF + IR * RF);
    const int tid = threadIdx.x;

    // All threads compute geometry in parallel.
    const float cy = (offs[2*b + 0] + 1.0f) * (H * 0.5f);
    const float cx = (offs[2*b + 1] + 1.0f) * (W * 0.5f);
    const float Ey = cy - (OUTHW * K - 1) * 0.5f;
    const float Ex = cx - (OUTHW * K - 1) * 0.5f;
    const int   y0 = (int)floorf(Ey);
    const int   x0 = (int)floorf(Ex);
    const float wy = Ey - (float)y0;
    const float wx = Ex - (float)x0;

    const int px0     = x0 + j0 * K;
    const int x_hi    = min(px0 + SPAN, W);
    const int start_f = (px0 * 3) & ~3;
    const int end_f   = min((x_hi * 3 + 3) & ~3, ROWFL);
    const int validf  = end_f - start_f;
    const int off0    = px0 * 3 - start_f;      // 0..3
    const int rowbytes = validf * 4;            // multiple of 16
    const int ytop    = y0 + i0 * K;

    // Warp 0: lane 0 inits mbars + fence + expectations; lanes 0-8 issue one
    // row copy each in parallel.
    if (tid < 32) {
        if (tid == 0) {
#pragma unroll
            for (int g = 0; g < 3; g++) mbar_init(smem_u32(smem + 2 * g), 1);
            asm volatile("fence.proxy.async.shared::cta;" ::: "memory");
#pragma unroll
            for (int g = 0; g < 3; g++) {
                int nv = 0;
#pragma unroll
                for (int r = 3*g; r < 3*g + 3; r++)
                    if ((unsigned)(ytop + r) < (unsigned)H) nv++;
                mbar_expect_tx(smem_u32(smem + 2 * g), (uint32_t)(nv * rowbytes));
            }
        }
        __syncwarp();
        if (tid < IR) {
            const int gy = ytop + tid;
            if ((unsigned)gy < (unsigned)H) {
                const float* src = img + ((size_t)b * H + gy) * ROWFL + start_f;
                bulk_g2s(smem_u32(tile + tid * RF), src, (uint32_t)rowbytes,
                         smem_u32(smem + 2 * (tid / 3)));
            }
        }
    }

    // Meanwhile: zero tails (disjoint from bulk-copy dest bytes) and OOB rows.
    {
        const int ntail = RF - validf;          // >= 3 always
        for (int idx = tid; idx < IR * ntail; idx += NT) {
            const int r = idx / ntail;
            tile[r * RF + validf + idx % ntail] = 0.0f;
        }
#pragma unroll
        for (int r = 0; r < IR; r++) {
            if ((unsigned)(ytop + r) >= (unsigned)H) {
                for (int f = tid; f < validf; f += NT) tile[r * RF + f] = 0.0f;
            }
        }
    }
    __syncthreads();   // zeros done + mbar inits visible to all warps

    // ── Phase A, pipelined per 3-row group. ──
    phaseA_pipelined<K>(smem, tile, hs, off0, wx);
    __syncthreads();

    // ── Phase B: vertical (K+1)-tap over hs. Conflict-free. ──
    constexpr float inv = 1.0f / (K * K);
    const float wy0 = 1.0f - wy;
    for (int o = tid; o < TILE_I * JW; o += NT) {
        const int ti = o / JW;
        const int jj = o % JW;
        float4 a = hs[(ti * K) * JW + jj];
        float o0 = wy0 * a.x, o1 = wy0 * a.y, o2 = wy0 * a.z;
#pragma unroll
        for (int p = 1; p < K; p++) {
            float4 m = hs[(ti * K + p) * JW + jj];
            o0 += m.x; o1 += m.y; o2 += m.z;
        }
        float4 e = hs[(ti * K + K) * JW + jj];
        o0 += wy * e.x; o1 += wy * e.y; o2 += wy * e.z;

        const size_t ob = (((size_t)b * OUTHW + (i0 + ti)) * OUTHW + (j0 + jj)) * (C * NDEPTH);
        out[ob + 0 * NDEPTH + D] = o0 * inv;
        out[ob + 1 * NDEPTH + D] = o1 * inv;
        out[ob + 2 * NDEPTH + D] = o2 * inv;
    }
}

__global__ __launch_bounds__(NT, 8)
void glimpse_fused(const float* __restrict__ img, const float* __restrict__ offs,
                   float* __restrict__ out)
{
    extern __shared__ float smem[];
    const int bid = blockIdx.x;
    if (bid < NBLK4) {                       // K=4: 64 blocks/image (32 row x 2 col)
        const int b = bid >> 6;
        const int t = bid & 63;
        glimpse_body<4, 2>(img, offs, out, smem, b, (t >> 1) * 2, (t & 1) * 32);
    } else if (bid < NBLK4 + NBLK2) {        // K=2: 16 blocks/image
        const int r = bid - NBLK4;
        glimpse_body<2, 1>(img, offs, out, smem, r >> 4, (r & 15) * 4, 0);
    } else {                                 // K=1: 8 blocks/image
        const int r = bid - (NBLK4 + NBLK2);
        glimpse_body<1, 0>(img, offs, out, smem, r >> 3, (r & 7) * 8, 0);
    }
}

extern "C" void kernel_launch(void* const* d_in, const int* in_sizes, int n_in,
                              void* d_out, int out_size)
{
    (void)in_sizes; (void)n_in; (void)out_size;
    const float* img  = (const float*)d_in[0];
    const float* offs = (const float*)d_in[1];
    float* out = (float*)d_out;

    cudaFuncSetAttribute(glimpse_fused, cudaFuncAttributeMaxDynamicSharedMemorySize, SMEM_BYTES);
    glimpse_fused<<<NBLK, NT, SMEM_BYTES>>>(img, offs, out);
}

// round 13
// speedup vs baseline: 1.0822x; 1.0822x over previous
#include <cuda_runtime.h>
#include <cstdint>
#include <math.h>

// SpatialGlimpse fused, one-shot blocks, two-phase separable stencil.
// R13: NT=128 + JW=32 for ALL depths -> max SMEM 18.9KB -> 12 CTAs/SM
// (SMEM-capped), 7168 blocks. 3-group mbarrier pipelining, parallel copy
// issue, conflict-free Phase A/B (stride-3K word lanes / consecutive f4).

static constexpr int BATCH  = 64;
static constexpr int H = 512, W = 512, C = 3;
static constexpr int OUTHW  = 64;
static constexpr int NDEPTH = 3;
static constexpr int ROWFL  = W * C;   // 1536 floats per image row
static constexpr int NT     = 128;
static constexpr int JW     = 32;      // output columns per block (all depths)

template<int K> struct Cfg;
template<> struct Cfg<1> { static constexpr int TILE_I = 8; static constexpr int ROWF = 112; static constexpr int NV = 3; };
template<> struct Cfg<2> { static constexpr int TILE_I = 4; static constexpr int ROWF = 204; static constexpr int NV = 3; };
template<> struct Cfg<4> { static constexpr int TILE_I = 2; static constexpr int ROWF = 396; static constexpr int NV = 5; };
// IR = TILE_I*K + 1 = 9 rows for every depth; 3 mbarrier groups of 3 rows.
// x-span = JW*K+1 pixels; ROWF covers max read index (a0max + 4*NV) + tail slack.

static constexpr int NBLK4 = BATCH * 32 * 2;   // 4096
static constexpr int NBLK2 = BATCH * 16 * 2;   // 2048
static constexpr int NBLK1 = BATCH * 8 * 2;    // 1024
static constexpr int NBLK  = NBLK4 + NBLK2 + NBLK1;   // 7168

// SMEM floats: [0,8) three mbarriers (8B at float idx 0,2,4) | tile 9*RF | hs 9*32 f4
static constexpr int TILE_OFF   = 8;
static constexpr int SMEM_BYTES = (TILE_OFF + 9 * 396 + 9 * JW * 4) * 4;   // 18896 (K=4 max)

__device__ __forceinline__ uint32_t smem_u32(const void* p) {
    return (uint32_t)__cvta_generic_to_shared(p);
}
__device__ __forceinline__ void mbar_init(uint32_t a, uint32_t cnt) {
    asm volatile("mbarrier.init.shared.b64 [%0], %1;" :: "r"(a), "r"(cnt) : "memory");
}
__device__ __forceinline__ void mbar_expect_tx(uint32_t a, uint32_t bytes) {
    asm volatile("mbarrier.arrive.expect_tx.shared.b64 _, [%0], %1;" :: "r"(a), "r"(bytes) : "memory");
}
__device__ __forceinline__ void mbar_wait(uint32_t a, uint32_t parity) {
    asm volatile(
        "{\n\t"
        ".reg .pred P;\n\t"
        "LAB_WAIT_%=:\n\t"
        "mbarrier.try_wait.parity.acquire.cta.shared::cta.b64 P, [%0], %1, 0x989680;\n\t"
        "@P bra LAB_DONE_%=;\n\t"
        "bra LAB_WAIT_%=;\n\t"
        "LAB_DONE_%=:\n\t"
        "}"
        :: "r"(a), "r"(parity) : "memory");
}
__device__ __forceinline__ void bulk_g2s(uint32_t dst, const void* src, uint32_t bytes, uint32_t mbar) {
    asm volatile(
        "cp.async.bulk.shared::cluster.global.mbarrier::complete_tx::bytes [%0], [%1], %2, [%3];"
        :: "r"(dst), "l"(src), "r"(bytes), "r"(mbar) : "memory");
}

// Horizontal weighted sum of one row window (K+1 pixels x 3 channels).
// SH = sub-float4 shift (compile-time so v[] stays in registers).
template<int K, int SH>
__device__ __forceinline__ void hreduce_one(const float* __restrict__ rowp, float wx, float4& h)
{
    constexpr int NV = Cfg<K>::NV;
    const float hx0 = 1.0f - wx;
    float v[4 * NV];
    const float4* rp = reinterpret_cast<const float4*>(rowp);
#pragma unroll
    for (int t = 0; t < NV; t++) {
        float4 q = rp[t];
        v[4*t+0] = q.x; v[4*t+1] = q.y; v[4*t+2] = q.z; v[4*t+3] = q.w;
    }
    float r0 = hx0 * v[SH + 0] + wx * v[SH + 3*K + 0];
    float r1 = hx0 * v[SH + 1] + wx * v[SH + 3*K + 1];
    float r2 = hx0 * v[SH + 2] + wx * v[SH + 3*K + 2];
#pragma unroll
    for (int q = 1; q < K; q++) {
        r0 += v[SH + 3*q + 0];
        r1 += v[SH + 3*q + 1];
        r2 += v[SH + 3*q + 2];
    }
    h.x = r0; h.y = r1; h.z = r2; h.w = 0.0f;
}

template<int K, int D>
__device__ __forceinline__ void glimpse_body(
    const float* __restrict__ img, const float* __restrict__ offs,
    float* __restrict__ out, float* smem, int b, int i0, int j0)
{
    constexpr int TILE_I = Cfg<K>::TILE_I;
    constexpr int RF     = Cfg<K>::ROWF;
    constexpr int IR     = 9;
    constexpr int SPAN   = JW * K + 1;

    float* tile = smem + TILE_OFF;
    float4* hs  = reinterpret_cast<float4*>(smem + TILE_OFF + IR * RF);
    const int tid = threadIdx.x;

    // All threads compute geometry in parallel.
    const float cy = (offs[2*b + 0] + 1.0f) * (H * 0.5f);
    const float cx = (offs[2*b + 1] + 1.0f) * (W * 0.5f);
    const float Ey = cy - (OUTHW * K - 1) * 0.5f;
    const float Ex = cx - (OUTHW * K - 1) * 0.5f;
    const int   y0 = (int)floorf(Ey);
    const int   x0 = (int)floorf(Ex);
    const float wy = Ey - (float)y0;
    const float wx = Ex - (float)x0;

    const int px0     = x0 + j0 * K;
    const int x_hi    = min(px0 + SPAN, W);
    const int start_f = (px0 * 3) & ~3;
    const int end_f   = min((x_hi * 3 + 3) & ~3, ROWFL);
    const int validf  = end_f - start_f;
    const int off0    = px0 * 3 - start_f;      // 0..3
    const int rowbytes = validf * 4;            // multiple of 16
    const int ytop    = y0 + i0 * K;

    // Warp 0: lane 0 inits mbars + fence + expectations; lanes 0-8 issue one
    // row copy each in parallel.
    if (tid < 32) {
        if (tid == 0) {
#pragma unroll
            for (int g = 0; g < 3; g++) mbar_init(smem_u32(smem + 2 * g), 1);
            asm volatile("fence.proxy.async.shared::cta;" ::: "memory");
#pragma unroll
            for (int g = 0; g < 3; g++) {
                int nv = 0;
#pragma unroll
                for (int r = 3*g; r < 3*g + 3; r++)
                    if ((unsigned)(ytop + r) < (unsigned)H) nv++;
                mbar_expect_tx(smem_u32(smem + 2 * g), (uint32_t)(nv * rowbytes));
            }
        }
        __syncwarp();
        if (tid < IR) {
            const int gy = ytop + tid;
            if ((unsigned)gy < (unsigned)H) {
                const float* src = img + ((size_t)b * H + gy) * ROWFL + start_f;
                bulk_g2s(smem_u32(tile + tid * RF), src, (uint32_t)rowbytes,
                         smem_u32(smem + 2 * (tid / 3)));
            }
        }
    }

    // Meanwhile: zero tails (disjoint from bulk-copy dest bytes) and OOB rows.
    {
        const int ntail = RF - validf;          // >= 4 always
        for (int idx = tid; idx < IR * ntail; idx += NT) {
            const int r = idx / ntail;
            tile[r * RF + validf + idx % ntail] = 0.0f;
        }
#pragma unroll
        for (int r = 0; r < IR; r++) {
            if ((unsigned)(ytop + r) >= (unsigned)H) {
                for (int f = tid; f < validf; f += NT) tile[r * RF + f] = 0.0f;
            }
        }
    }
    __syncthreads();   // zeros done + mbar inits visible to all warps

    // ── Phase A, pipelined per 3-row group: 96 active threads (3 rows x 32 j). ──
    if (tid < 3 * JW) {
        const int jA   = tid & (JW - 1);
        const int rsub = tid >> 5;               // 0..2
        const int sidx = off0 + 3 * K * jA;
        const float* colp = tile + (sidx & ~3);
        const int sh = sidx & 3;
#pragma unroll
        for (int g = 0; g < 3; g++) {
            mbar_wait(smem_u32(smem + 2 * g), 0);
            const int r = 3 * g + rsub;
            const float* rowp = colp + r * RF;
            float4 h;
            switch (sh) {
            case 0:  hreduce_one<K,0>(rowp, wx, h); break;
            case 1:  hreduce_one<K,1>(rowp, wx, h); break;
            case 2:  hreduce_one<K,2>(rowp, wx, h); break;
            default: hreduce_one<K,3>(rowp, wx, h); break;
            }
            hs[r * JW + jA] = h;
        }
    }
    __syncthreads();

    // ── Phase B: vertical (K+1)-tap over hs. Conflict-free. ──
    constexpr float inv = 1.0f / (K * K);
    const float wy0 = 1.0f - wy;
    for (int o = tid; o < TILE_I * JW; o += NT) {
        const int ti = o >> 5;
        const int jj = o & (JW - 1);
        float4 a = hs[(ti * K) * JW + jj];
        float o0 = wy0 * a.x, o1 = wy0 * a.y, o2 = wy0 * a.z;
#pragma unroll
        for (int p = 1; p < K; p++) {
            float4 m = hs[(ti * K + p) * JW + jj];
            o0 += m.x; o1 += m.y; o2 += m.z;
        }
        float4 e = hs[(ti * K + K) * JW + jj];
        o0 += wy * e.x; o1 += wy * e.y; o2 += wy * e.z;

        const size_t ob = (((size_t)b * OUTHW + (i0 + ti)) * OUTHW + (j0 + jj)) * (C * NDEPTH);
        out[ob + 0 * NDEPTH + D] = o0 * inv;
        out[ob + 1 * NDEPTH + D] = o1 * inv;
        out[ob + 2 * NDEPTH + D] = o2 * inv;
    }
}

__global__ __launch_bounds__(NT, 12)
void glimpse_fused(const float* __restrict__ img, const float* __restrict__ offs,
                   float* __restrict__ out)
{
    extern __shared__ float smem[];
    const int bid = blockIdx.x;
    if (bid < NBLK4) {                       // K=4: 64 blocks/image (32 row x 2 col)
        const int b = bid >> 6;
        const int t = bid & 63;
        glimpse_body<4, 2>(img, offs, out, smem, b, (t >> 1) * 2, (t & 1) * JW);
    } else if (bid < NBLK4 + NBLK2) {        // K=2: 32 blocks/image (16 row x 2 col)
        const int r = bid - NBLK4;
        const int b = r >> 5;
        const int t = r & 31;
        glimpse_body<2, 1>(img, offs, out, smem, b, (t >> 1) * 4, (t & 1) * JW);
    } else {                                 // K=1: 16 blocks/image (8 row x 2 col)
        const int r = bid - (NBLK4 + NBLK2);
        const int b = r >> 4;
        const int t = r & 15;
        glimpse_body<1, 0>(img, offs, out, smem, b, (t >> 1) * 8, (t & 1) * JW);
    }
}

extern "C" void kernel_launch(void* const* d_in, const int* in_sizes, int n_in,
                              void* d_out, int out_size)
{
    (void)in_sizes; (void)n_in; (void)out_size;
    const float* img  = (const float*)d_in[0];
    const float* offs = (const float*)d_in[1];
    float* out = (float*)d_out;

    cudaFuncSetAttribute(glimpse_fused, cudaFuncAttributeMaxDynamicSharedMemorySize, SMEM_BYTES);
    glimpse_fused<<<NBLK, NT, SMEM_BYTES>>>(img, offs, out);
}